// round 12
// baseline (speedup 1.0000x reference)
#include <cuda_runtime.h>
#include <cuda_bf16.h>
#include <math.h>

#define Bn   64
#define Sn   512
#define EMBn 128
#define HIDn 256
#define G4   1024
#define NTAG 9

// -------- persistent device scratch (no runtime allocs allowed) --------
__device__ float g_xz  [2u*Bn*Sn*G4];    // ((d*64+b)*512+s)*1024 + g
__device__ float g_hall[2u*Bn*Sn*HIDn];  // ((d*64+b)*512+s)*256  + j
__device__ int   g_lens[Bn];
__device__ int   g_flags[4][2][16];      // [bg][dir][hg] step flags
// split-bf16 operands for the tensor input GEMM
__device__ __nv_bfloat16 g_xc_hi[32768u*128];   // gathered emb rows [m][k], hi
__device__ __nv_bfloat16 g_xc_lo[32768u*128];   // lo
__device__ __nv_bfloat16 g_wt_hi[2u*1024*128];  // W^T rows [d*1024+n][k], hi
__device__ __nv_bfloat16 g_wt_lo[2u*1024*128];  // lo
// split-bf16 U (reordered cols n' = unit*4 + gate) for tensor LSTM
__device__ __nv_bfloat16 g_u2h[2u*1024*256];    // [d*1024+n'][k]
__device__ __nv_bfloat16 g_u2l[2u*1024*256];
// split-bf16 h exchange (per step)
__device__ __nv_bfloat16 g_hx_hi[2u*Bn*Sn*HIDn];
__device__ __nv_bfloat16 g_hx_lo[2u*Bn*Sn*HIDn];

__global__ void k_reset() {
    int t = threadIdx.x;
    if (t < 4*2*16) ((int*)g_flags)[t] = 0;
}

// ---------------- mma.sync helpers (compute_103-safe) ------------------
__device__ __forceinline__ unsigned smem_u32(const void* p) {
    unsigned a;
    asm("{ .reg .u64 t; cvta.to.shared.u64 t, %1; cvt.u32.u64 %0, t; }"
        : "=r"(a) : "l"(p));
    return a;
}
__device__ __forceinline__ void ldsm4(unsigned* r, unsigned addr) {
    asm volatile("ldmatrix.sync.aligned.m8n8.x4.shared.b16 {%0,%1,%2,%3}, [%4];"
        : "=r"(r[0]), "=r"(r[1]), "=r"(r[2]), "=r"(r[3]) : "r"(addr));
}
__device__ __forceinline__ void ldsm2(unsigned& r0, unsigned& r1, unsigned addr) {
    asm volatile("ldmatrix.sync.aligned.m8n8.x2.shared.b16 {%0,%1}, [%2];"
        : "=r"(r0), "=r"(r1) : "r"(addr));
}
__device__ __forceinline__ void mma16816(float* c, const unsigned* a,
                                         unsigned b0, unsigned b1) {
    asm volatile("mma.sync.aligned.m16n8k16.row.col.f32.bf16.bf16.f32 "
        "{%0,%1,%2,%3}, {%4,%5,%6,%7}, {%8,%9}, {%0,%1,%2,%3};"
        : "+f"(c[0]), "+f"(c[1]), "+f"(c[2]), "+f"(c[3])
        : "r"(a[0]), "r"(a[1]), "r"(a[2]), "r"(a[3]), "r"(b0), "r"(b1));
}

// ---------------- lens: count nonzero tokens per row -------------------
__global__ void k_lens(const int* __restrict__ text, float* __restrict__ out_lens) {
    int b = blockIdx.x, lane = threadIdx.x;
    int cnt = 0;
    for (int s = lane; s < Sn; s += 32) cnt += (text[b*Sn + s] != 0);
    for (int o = 16; o > 0; o >>= 1) cnt += __shfl_down_sync(0xffffffffu, cnt, o);
    if (lane == 0) { g_lens[b] = cnt; out_lens[b] = (float)cnt; }
}

// -------- prep: gathered embeddings -> hi/lo bf16 ----------------------
__global__ __launch_bounds__(128) void k_prepX(const int* __restrict__ text,
                                               const float* __restrict__ emb) {
    int m = blockIdx.x * 128 + threadIdx.x;     // 256 blocks
    int tok = text[m];
    const float4* er = (const float4*)(emb + (long)tok * EMBn);
    uint4* dh = ((uint4*)g_xc_hi) + (long)m * 16;
    uint4* dl = ((uint4*)g_xc_lo) + (long)m * 16;
    #pragma unroll 4
    for (int i = 0; i < 16; i++) {
        float4 a = er[2*i], b = er[2*i+1];
        float2 p0 = make_float2(a.x, a.y), p1 = make_float2(a.z, a.w);
        float2 p2 = make_float2(b.x, b.y), p3 = make_float2(b.z, b.w);
        __nv_bfloat162 h0 = __float22bfloat162_rn(p0);
        __nv_bfloat162 h1 = __float22bfloat162_rn(p1);
        __nv_bfloat162 h2 = __float22bfloat162_rn(p2);
        __nv_bfloat162 h3 = __float22bfloat162_rn(p3);
        float2 f0 = __bfloat1622float2(h0), f1 = __bfloat1622float2(h1);
        float2 f2 = __bfloat1622float2(h2), f3 = __bfloat1622float2(h3);
        __nv_bfloat162 l0 = __float22bfloat162_rn(make_float2(p0.x-f0.x, p0.y-f0.y));
        __nv_bfloat162 l1 = __float22bfloat162_rn(make_float2(p1.x-f1.x, p1.y-f1.y));
        __nv_bfloat162 l2 = __float22bfloat162_rn(make_float2(p2.x-f2.x, p2.y-f2.y));
        __nv_bfloat162 l3 = __float22bfloat162_rn(make_float2(p3.x-f3.x, p3.y-f3.y));
        uint4 uh, ul;
        uh.x = *(unsigned*)&h0; uh.y = *(unsigned*)&h1;
        uh.z = *(unsigned*)&h2; uh.w = *(unsigned*)&h3;
        ul.x = *(unsigned*)&l0; ul.y = *(unsigned*)&l1;
        ul.z = *(unsigned*)&l2; ul.w = *(unsigned*)&l3;
        dh[i] = uh; dl[i] = ul;
    }
}

// -------- prep: W^T -> hi/lo bf16, one thread per element --------------
__global__ __launch_bounds__(256) void k_prepW(const float* __restrict__ Wf,
                                               const float* __restrict__ Wb) {
    int gid = blockIdx.x * 256 + threadIdx.x;   // 1024 blocks -> 262144
    int k = gid & 127;
    int n = (gid >> 7) & 1023;
    int d = gid >> 17;
    const float* W = d ? Wb : Wf;
    float v = W[k * G4 + n];
    __nv_bfloat16 h = __float2bfloat16_rn(v);
    long o = ((long)(d*1024 + n))*128 + k;
    g_wt_hi[o] = h;
    g_wt_lo[o] = __float2bfloat16_rn(v - __bfloat162float(h));
}

// -------- prep: U reorder (n' = unit*4+gate), one thread per element ----
__global__ __launch_bounds__(256) void k_prepU(const float* __restrict__ Uf,
                                               const float* __restrict__ Ub) {
    int gid = blockIdx.x * 256 + threadIdx.x;   // 2048 blocks -> 524288
    int k  = gid & 255;
    int np = (gid >> 8) & 1023;
    int d  = gid >> 18;
    int j = np >> 2, g = np & 3;
    const float* U = d ? Ub : Uf;
    float v = U[k * G4 + g*256 + j];
    __nv_bfloat16 h = __float2bfloat16_rn(v);
    long o = ((long)(d*1024 + np))*256 + k;
    g_u2h[o] = h;
    g_u2l[o] = __float2bfloat16_rn(v - __bfloat162float(h));
}

// -------- tensor input GEMM via mma.sync (split-bf16) — R9 proven ------
#define TGA 0
#define TGB0 34816
#define TGB1 69632
#define TG_SMEM 104448

__global__ __launch_bounds__(256) void k_tgemm(const float* __restrict__ bf_,
                                               const float* __restrict__ bb_) {
    extern __shared__ char smem[];
    unsigned sb = smem_u32(smem);
    int tid = threadIdx.x, wid = tid >> 5, lane = tid & 31;
    int wr = wid >> 1, wc = wid & 1;
    int m0 = blockIdx.y * 128;
    int n0 = blockIdx.x * 128;
    int d  = n0 >> 10, gg0 = n0 & 1023;

    {
        int row = tid >> 1, half = tid & 1;
        const uint4* s0 = ((const uint4*)g_wt_hi) + (long)(d*1024 + gg0 + row)*16 + half*8;
        const uint4* s1 = ((const uint4*)g_wt_lo) + (long)(d*1024 + gg0 + row)*16 + half*8;
        uint4* d0 = (uint4*)(smem + TGB0 + row*272 + half*128);
        uint4* d1 = (uint4*)(smem + TGB1 + row*272 + half*128);
        #pragma unroll
        for (int i = 0; i < 8; i++) { d0[i] = s0[i]; d1[i] = s1[i]; }
    }
    {
        int row = tid >> 1, half = tid & 1;
        const uint4* s = ((const uint4*)g_xc_hi) + (long)(m0 + row)*16 + half*8;
        uint4* dA = (uint4*)(smem + TGA + row*272 + half*128);
        #pragma unroll
        for (int i = 0; i < 8; i++) dA[i] = s[i];
    }
    __syncthreads();

    float acc[2][8][4];
    #pragma unroll
    for (int mi = 0; mi < 2; mi++)
        #pragma unroll
        for (int nj = 0; nj < 8; nj++)
            #pragma unroll
            for (int q = 0; q < 4; q++) acc[mi][nj][q] = 0.f;

    unsigned a_row = (unsigned)(wr*32 + (lane & 15));
    unsigned b_rowbase = (unsigned)(wc*64 + (lane & 7));
    unsigned a_koff = (unsigned)((lane >> 4) * 8);
    unsigned b_koff = (unsigned)(((lane >> 3) & 1) * 8);

    #pragma unroll 1
    for (int phase = 0; phase < 2; phase++) {
        if (phase == 1) {
            __syncthreads();
            int row = tid >> 1, half = tid & 1;
            const uint4* s = ((const uint4*)g_xc_lo) + (long)(m0 + row)*16 + half*8;
            uint4* dA = (uint4*)(smem + TGA + row*272 + half*128);
            #pragma unroll
            for (int i = 0; i < 8; i++) dA[i] = s[i];
            __syncthreads();
        }
        #pragma unroll
        for (int kt = 0; kt < 8; kt++) {
            unsigned a0[4], a1[4];
            unsigned aaddr = sb + TGA + a_row*272 + (kt*16 + a_koff)*2;
            ldsm4(a0, aaddr);
            ldsm4(a1, aaddr + 16*272);
            #pragma unroll
            for (int nj = 0; nj < 8; nj++) {
                unsigned boff = (b_rowbase + nj*8)*272 + (kt*16 + b_koff)*2;
                unsigned b0, b1;
                ldsm2(b0, b1, sb + TGB0 + boff);
                mma16816(acc[0][nj], a0, b0, b1);
                mma16816(acc[1][nj], a1, b0, b1);
                if (phase == 0) {
                    unsigned c0, c1;
                    ldsm2(c0, c1, sb + TGB1 + boff);
                    mma16816(acc[0][nj], a0, c0, c1);
                    mma16816(acc[1][nj], a1, c0, c1);
                }
            }
        }
    }

    const float* bias = d ? bb_ : bf_;
    #pragma unroll
    for (int mi = 0; mi < 2; mi++) {
        int m = m0 + wr*32 + mi*16 + (lane >> 2);
        float* rowp = g_xz + ((long)d*32768 + m)*G4;
        #pragma unroll
        for (int nj = 0; nj < 8; nj++) {
            int gg = gg0 + wc*64 + nj*8 + (lane & 3)*2;
            float bx = bias[gg], by = bias[gg+1];
            float2 v0, v1;
            v0.x = acc[mi][nj][0] + bx; v0.y = acc[mi][nj][1] + by;
            v1.x = acc[mi][nj][2] + bx; v1.y = acc[mi][nj][3] + by;
            *(float2*)(rowp + gg)          = v0;
            *(float2*)(rowp + 8*G4 + gg)   = v1;
        }
    }
}

// ------------- dual-direction tensor-core persistent BiLSTM ------------
// 64 blocks = (hg 0..15, bg 0..3), 256 threads = 8 warps. Block owns units
// [hg*16,+16), batches [bg*16,+16), BOTH directions. Per iteration: F phase
// then B phase; each phase's peer-flag wait is hidden behind the other
// phase's compute. Flags: g_flags[bg][dir][hg] (16 parallel pollers).
// smem: U'F hi/lo, U'B hi/lo (64 rows * 528 ea), then 4 A stages (16*528).
#define LU_FH 0
#define LU_FL 33792
#define LU_BH 67584
#define LU_BL 101376
#define LA_FH 135168
#define LA_FL (135168 + 8448)
#define LA_BH (135168 + 2*8448)
#define LA_BL (135168 + 3*8448)
#define LS_SMEM (135168 + 4*8448)

__global__ __launch_bounds__(256) void k_lstm() {
    extern __shared__ char smem[];
    unsigned sb = smem_u32(smem);

    int blk = blockIdx.x;
    int hg = blk >> 2;
    int bg = blk & 3;
    int b0 = bg * 16;

    int tid = threadIdx.x, wid = tid >> 5, lane = tid & 31;
    int nj = wid;

    // stage U' rows [hg*64,+64) for both dirs, hi+lo
    for (int i = tid; i < 64*32; i += 256) {
        int row = i >> 5, c = i & 31;
        long srcF = ((long)(hg*64 + row)) * 256;
        long srcB = ((long)(1024 + hg*64 + row)) * 256;
        *(uint4*)(smem + LU_FH + row*528 + c*16) = *(((const uint4*)(g_u2h + srcF)) + c);
        *(uint4*)(smem + LU_FL + row*528 + c*16) = *(((const uint4*)(g_u2l + srcF)) + c);
        *(uint4*)(smem + LU_BH + row*528 + c*16) = *(((const uint4*)(g_u2h + srcB)) + c);
        *(uint4*)(smem + LU_BL + row*528 + c*16) = *(((const uint4*)(g_u2l + srcB)) + c);
    }
    // zero A stages (h0 = 0): 4 * 8448 B = 8448 floats
    for (int i = tid; i < 8448; i += 256)
        *(float*)(smem + LA_FH + i*4) = 0.f;
    __syncthreads();

    // preload B fragments for both dirs (128 regs)
    unsigned bhF[16][2], blF[16][2], bhB[16][2], blB[16][2];
    {
        unsigned brow = (unsigned)(nj*8 + (lane & 7));
        unsigned koff = (unsigned)(((lane >> 3) & 1) * 8);
        #pragma unroll
        for (int kt = 0; kt < 16; kt++) {
            unsigned o = brow*528 + (kt*16 + koff)*2;
            ldsm2(bhF[kt][0], bhF[kt][1], sb + LU_FH + o);
            ldsm2(blF[kt][0], blF[kt][1], sb + LU_FL + o);
            ldsm2(bhB[kt][0], bhB[kt][1], sb + LU_BH + o);
            ldsm2(blB[kt][0], blB[kt][1], sb + LU_BL + o);
        }
    }

    int row = lane >> 2;
    int p   = lane & 3;
    int jj  = nj*2 + (p >> 1);
    int jgl = hg*16 + jj;
    bool fin = (lane & 1) == 0;
    float cF0 = 0.f, cF1 = 0.f, cB0 = 0.f, cB1 = 0.f;

    unsigned a_row = (unsigned)(lane & 15);
    unsigned a_koff = (unsigned)((lane >> 4) * 8);
    unsigned aoff = a_row*528 + a_koff*2;

    volatile int* myFlagF = &g_flags[bg][0][hg];
    volatile int* myFlagB = &g_flags[bg][1][hg];

    for (int r = 0; r < Sn; r++) {
        int sf = r, sbk = Sn - 1 - r;

        // ---------- FORWARD phase (d=0, step sf) ----------
        float x0=0,x1=0,x2=0,x3=0,x4=0,x5=0,x6=0,x7=0;
        if (fin) {
            const float* xp = g_xz + (((long)(b0 + row))*Sn + sf)*G4 + jgl;
            x0 = __ldg(xp);       x1 = __ldg(xp + 256);
            x2 = __ldg(xp + 512); x3 = __ldg(xp + 768);
            const float* xq = xp + (long)8*Sn*G4;
            x4 = __ldg(xq);       x5 = __ldg(xq + 256);
            x6 = __ldg(xq + 512); x7 = __ldg(xq + 768);
        }
        if (r > 0) {
            if (tid < 16) {
                volatile int* f = &g_flags[bg][0][tid];
                while (*f < r) { }
            }
            __syncthreads();
            int sp = sf - 1;
            #pragma unroll
            for (int i = 0; i < 2; i++) {
                int l = i*256 + tid;
                int ar = l >> 5, c = l & 31;
                long src = (((long)(b0 + ar))*Sn + sp)*HIDn;
                *(uint4*)(smem + LA_FH + ar*528 + c*16) = __ldcg(((const uint4*)(g_hx_hi + src)) + c);
                *(uint4*)(smem + LA_FL + ar*528 + c*16) = __ldcg(((const uint4*)(g_hx_lo + src)) + c);
            }
        }
        __syncthreads();

        {
            float aA[4] = {0,0,0,0}, aB[4] = {0,0,0,0}, aC[4] = {0,0,0,0};
            #pragma unroll
            for (int kt = 0; kt < 16; kt++) {
                unsigned ah[4], al[4];
                ldsm4(ah, sb + LA_FH + aoff + kt*32);
                mma16816(aA, ah, bhF[kt][0], bhF[kt][1]);
                mma16816(aB, ah, blF[kt][0], blF[kt][1]);
                ldsm4(al, sb + LA_FL + aoff + kt*32);
                mma16816(aC, al, bhF[kt][0], bhF[kt][1]);
            }
            float acc0 = aA[0]+aB[0]+aC[0], acc1 = aA[1]+aB[1]+aC[1];
            float acc2 = aA[2]+aB[2]+aC[2], acc3 = aA[3]+aB[3]+aC[3];
            float rc0 = __shfl_xor_sync(0xffffffffu, acc0, 1);
            float rc1 = __shfl_xor_sync(0xffffffffu, acc1, 1);
            float rc2 = __shfl_xor_sync(0xffffffffu, acc2, 1);
            float rc3 = __shfl_xor_sync(0xffffffffu, acc3, 1);
            if (fin) {
                {
                    float zi = x0 + acc0, zf = x1 + acc1;
                    float zg = x2 + rc0,  zo = x3 + rc1;
                    float ig = 1.f/(1.f+__expf(-zi)), fg = 1.f/(1.f+__expf(-zf));
                    float gv = tanhf(zg), og = 1.f/(1.f+__expf(-zo));
                    cF0 = fg*cF0 + ig*gv;
                    float hv = og * tanhf(cF0);
                    long o0 = (((long)(b0 + row))*Sn + sf)*HIDn + jgl;
                    g_hall[o0] = hv;
                    __nv_bfloat16 hh = __float2bfloat16_rn(hv);
                    g_hx_hi[o0] = hh;
                    g_hx_lo[o0] = __float2bfloat16_rn(hv - __bfloat162float(hh));
                }
                {
                    float zi = x4 + acc2, zf = x5 + acc3;
                    float zg = x6 + rc2,  zo = x7 + rc3;
                    float ig = 1.f/(1.f+__expf(-zi)), fg = 1.f/(1.f+__expf(-zf));
                    float gv = tanhf(zg), og = 1.f/(1.f+__expf(-zo));
                    cF1 = fg*cF1 + ig*gv;
                    float hv = og * tanhf(cF1);
                    long o1 = (((long)(b0 + row + 8))*Sn + sf)*HIDn + jgl;
                    g_hall[o1] = hv;
                    __nv_bfloat16 hh = __float2bfloat16_rn(hv);
                    g_hx_hi[o1] = hh;
                    g_hx_lo[o1] = __float2bfloat16_rn(hv - __bfloat162float(hh));
                }
            }
        }
        __syncthreads();
        if (tid == 0) { __threadfence(); *myFlagF = r + 1; }

        // ---------- BACKWARD phase (d=1, step sbk) ----------
        if (fin) {
            const float* xp = g_xz + (((long)(64 + b0 + row))*Sn + sbk)*G4 + jgl;
            x0 = __ldg(xp);       x1 = __ldg(xp + 256);
            x2 = __ldg(xp + 512); x3 = __ldg(xp + 768);
            const float* xq = xp + (long)8*Sn*G4;
            x4 = __ldg(xq);       x5 = __ldg(xq + 256);
            x6 = __ldg(xq + 512); x7 = __ldg(xq + 768);
        }
        if (r > 0) {
            if (tid < 16) {
                volatile int* f = &g_flags[bg][1][tid];
                while (*f < r) { }
            }
            __syncthreads();
            int sp = sbk + 1;
            #pragma unroll
            for (int i = 0; i < 2; i++) {
                int l = i*256 + tid;
                int ar = l >> 5, c = l & 31;
                long src = (((long)(64 + b0 + ar))*Sn + sp)*HIDn;
                *(uint4*)(smem + LA_BH + ar*528 + c*16) = __ldcg(((const uint4*)(g_hx_hi + src)) + c);
                *(uint4*)(smem + LA_BL + ar*528 + c*16) = __ldcg(((const uint4*)(g_hx_lo + src)) + c);
            }
        }
        __syncthreads();

        {
            float aA[4] = {0,0,0,0}, aB[4] = {0,0,0,0}, aC[4] = {0,0,0,0};
            #pragma unroll
            for (int kt = 0; kt < 16; kt++) {
                unsigned ah[4], al[4];
                ldsm4(ah, sb + LA_BH + aoff + kt*32);
                mma16816(aA, ah, bhB[kt][0], bhB[kt][1]);
                mma16816(aB, ah, blB[kt][0], blB[kt][1]);
                ldsm4(al, sb + LA_BL + aoff + kt*32);
                mma16816(aC, al, bhB[kt][0], bhB[kt][1]);
            }
            float acc0 = aA[0]+aB[0]+aC[0], acc1 = aA[1]+aB[1]+aC[1];
            float acc2 = aA[2]+aB[2]+aC[2], acc3 = aA[3]+aB[3]+aC[3];
            float rc0 = __shfl_xor_sync(0xffffffffu, acc0, 1);
            float rc1 = __shfl_xor_sync(0xffffffffu, acc1, 1);
            float rc2 = __shfl_xor_sync(0xffffffffu, acc2, 1);
            float rc3 = __shfl_xor_sync(0xffffffffu, acc3, 1);
            if (fin) {
                {
                    float zi = x0 + acc0, zf = x1 + acc1;
                    float zg = x2 + rc0,  zo = x3 + rc1;
                    float ig = 1.f/(1.f+__expf(-zi)), fg = 1.f/(1.f+__expf(-zf));
                    float gv = tanhf(zg), og = 1.f/(1.f+__expf(-zo));
                    cB0 = fg*cB0 + ig*gv;
                    float hv = og * tanhf(cB0);
                    long o0 = (((long)(64 + b0 + row))*Sn + sbk)*HIDn + jgl;
                    g_hall[o0] = hv;
                    __nv_bfloat16 hh = __float2bfloat16_rn(hv);
                    g_hx_hi[o0] = hh;
                    g_hx_lo[o0] = __float2bfloat16_rn(hv - __bfloat162float(hh));
                }
                {
                    float zi = x4 + acc2, zf = x5 + acc3;
                    float zg = x6 + rc2,  zo = x7 + rc3;
                    float ig = 1.f/(1.f+__expf(-zi)), fg = 1.f/(1.f+__expf(-zf));
                    float gv = tanhf(zg), og = 1.f/(1.f+__expf(-zo));
                    cB1 = fg*cB1 + ig*gv;
                    float hv = og * tanhf(cB1);
                    long o1 = (((long)(64 + b0 + row + 8))*Sn + sbk)*HIDn + jgl;
                    g_hall[o1] = hv;
                    __nv_bfloat16 hh = __float2bfloat16_rn(hv);
                    g_hx_hi[o1] = hh;
                    g_hx_lo[o1] = __float2bfloat16_rn(hv - __bfloat162float(hh));
                }
            }
        }
        __syncthreads();
        if (tid == 0) { __threadfence(); *myFlagB = r + 1; }
    }
}

// ---------------- logits = [h_fwd ; h_bwd] @ W_d + b_d ------------------
__global__ __launch_bounds__(256) void k_logits(
    const float* __restrict__ Wd, const float* __restrict__ bd,
    float* __restrict__ out)
{
    __shared__ float Wd_s[512*NTAG];
    int tid = threadIdx.x;
    for (int i = tid; i < 512*NTAG; i += 256) Wd_s[i] = Wd[i];
    __syncthreads();

    int wid = tid >> 5, lane = tid & 31;
    long m = (long)blockIdx.x * 8 + wid;

    float acc[NTAG];
    #pragma unroll
    for (int t = 0; t < NTAG; t++) acc[t] = 0.f;

    for (int k = lane; k < 512; k += 32) {
        int dd = k >> 8, jj = k & 255;
        float hv = g_hall[((long)dd*32768 + m)*HIDn + jj];
        #pragma unroll
        for (int t = 0; t < NTAG; t++) acc[t] += hv * Wd_s[k*NTAG + t];
    }
    #pragma unroll
    for (int t = 0; t < NTAG; t++)
        for (int o = 16; o > 0; o >>= 1)
            acc[t] += __shfl_down_sync(0xffffffffu, acc[t], o);
    if (lane == 0) {
        #pragma unroll
        for (int t = 0; t < NTAG; t++) out[m*NTAG + t] = acc[t] + bd[t];
    }
}

// --------------------------- CRF (warp per batch) -----------------------
__global__ __launch_bounds__(256) void k_crf(
    const float* __restrict__ logits, const int* __restrict__ labels,
    const float* __restrict__ trans, float* __restrict__ out_ll)
{
    __shared__ float tr[81];
    __shared__ float alpha[8][12];
    int tid = threadIdx.x;
    if (tid < 81) tr[tid] = trans[tid];
    __syncthreads();

    int wid = tid >> 5, lane = tid & 31;
    int b = blockIdx.x * 8 + wid;
    int len = g_lens[b];
    const float* lg = logits + (long)b * Sn * NTAG;
    const int*   lb = labels + (long)b * Sn;

    float sc = 0.f;
    for (int t = lane; t < Sn; t += 32) {
        int y = lb[t];
        if (t < len)     sc += lg[t*NTAG + y];
        if (t < len - 1) sc += tr[y*NTAG + lb[t+1]];
    }
    for (int o = 16; o > 0; o >>= 1) sc += __shfl_down_sync(0xffffffffu, sc, o);
    sc = __shfl_sync(0xffffffffu, sc, 0);

    if (lane < NTAG) alpha[wid][lane] = lg[lane];
    __syncwarp();
    for (int t = 1; t < Sn; t++) {
        if (t >= len) break;
        float na = 0.f;
        if (lane < NTAG) {
            float mx = -1e30f;
            #pragma unroll
            for (int i = 0; i < NTAG; i++) {
                float v = alpha[wid][i] + tr[i*NTAG + lane];
                mx = fmaxf(mx, v);
            }
            float s = 0.f;
            #pragma unroll
            for (int i = 0; i < NTAG; i++)
                s += __expf(alpha[wid][i] + tr[i*NTAG + lane] - mx);
            na = mx + __logf(s) + lg[t*NTAG + lane];
        }
        __syncwarp();
        if (lane < NTAG) alpha[wid][lane] = na;
        __syncwarp();
    }
    if (lane == 0) {
        float mx = -1e30f;
        for (int i = 0; i < NTAG; i++) mx = fmaxf(mx, alpha[wid][i]);
        float s = 0.f;
        for (int i = 0; i < NTAG; i++) s += __expf(alpha[wid][i] - mx);
        out_ll[b] = sc - (mx + __logf(s));
    }
}

// ----------------------------------------------------------------------
extern "C" void kernel_launch(void* const* d_in, const int* in_sizes, int n_in,
                              void* d_out, int out_size)
{
    const int*   text  = (const int*)  d_in[0];
    const int*   labels= (const int*)  d_in[1];
    const float* emb   = (const float*)d_in[2];
    const float* Wf    = (const float*)d_in[3];
    const float* Uf    = (const float*)d_in[4];
    const float* bf    = (const float*)d_in[5];
    const float* Wb    = (const float*)d_in[6];
    const float* Ub    = (const float*)d_in[7];
    const float* bb    = (const float*)d_in[8];
    const float* Wd    = (const float*)d_in[9];
    const float* bd    = (const float*)d_in[10];
    const float* trans = (const float*)d_in[11];

    float* out        = (float*)d_out;
    float* out_logits = out;                         // 64*512*9
    float* out_lens   = out + 64ll*512*9;            // 64
    float* out_ll     = out_lens + 64;               // 64

    cudaFuncSetAttribute(k_lstm, cudaFuncAttributeMaxDynamicSharedMemorySize, LS_SMEM);
    cudaFuncSetAttribute(k_tgemm, cudaFuncAttributeMaxDynamicSharedMemorySize, TG_SMEM);

    k_reset<<<1, 128>>>();
    k_lens<<<64, 32>>>(text, out_lens);
    k_prepW<<<1024, 256>>>(Wf, Wb);
    k_prepU<<<2048, 256>>>(Uf, Ub);
    k_prepX<<<256, 128>>>(text, emb);
    dim3 tg(16, 256);
    k_tgemm<<<tg, 256, TG_SMEM>>>(bf, bb);
    k_lstm<<<64, 256, LS_SMEM>>>();
    k_logits<<<4096, 256>>>(Wd, bd, out_logits);
    k_crf<<<8, 256>>>(out_logits, labels, trans, out_ll);
}

// round 13
// speedup vs baseline: 1.5334x; 1.5334x over previous
#include <cuda_runtime.h>
#include <cuda_bf16.h>
#include <math.h>

#define Bn   64
#define Sn   512
#define EMBn 128
#define HIDn 256
#define G4   1024
#define NTAG 9

// -------- persistent device scratch (no runtime allocs allowed) --------
__device__ float g_xz  [2u*Bn*Sn*G4];    // ((d*64+b)*512+s)*1024 + g
__device__ float g_hall[2u*Bn*Sn*HIDn];  // ((d*64+b)*512+s)*256  + j
__device__ int   g_lens[Bn];
__device__ int   g_flags[8][16];         // [group = d*4+bg][member hg]
// split-bf16 operands for the tensor input GEMM
__device__ __nv_bfloat16 g_xc_hi[32768u*128];   // gathered emb rows [m][k], hi
__device__ __nv_bfloat16 g_xc_lo[32768u*128];   // lo
__device__ __nv_bfloat16 g_wt_hi[2u*1024*128];  // W^T rows [d*1024+n][k], hi
__device__ __nv_bfloat16 g_wt_lo[2u*1024*128];  // lo
// split-bf16 U (reordered cols n' = unit*4 + gate) for tensor LSTM
__device__ __nv_bfloat16 g_u2h[2u*1024*256];    // [d*1024+n'][k]
__device__ __nv_bfloat16 g_u2l[2u*1024*256];
// split-bf16 h exchange (per step)
__device__ __nv_bfloat16 g_hx_hi[2u*Bn*Sn*HIDn];
__device__ __nv_bfloat16 g_hx_lo[2u*Bn*Sn*HIDn];

__global__ void k_reset() {
    int t = threadIdx.x;
    if (t < 8*16) ((int*)g_flags)[t] = 0;
}

// ---------------- mma.sync helpers (compute_103-safe) ------------------
__device__ __forceinline__ unsigned smem_u32(const void* p) {
    unsigned a;
    asm("{ .reg .u64 t; cvta.to.shared.u64 t, %1; cvt.u32.u64 %0, t; }"
        : "=r"(a) : "l"(p));
    return a;
}
__device__ __forceinline__ void ldsm4(unsigned* r, unsigned addr) {
    asm volatile("ldmatrix.sync.aligned.m8n8.x4.shared.b16 {%0,%1,%2,%3}, [%4];"
        : "=r"(r[0]), "=r"(r[1]), "=r"(r[2]), "=r"(r[3]) : "r"(addr));
}
__device__ __forceinline__ void ldsm2(unsigned& r0, unsigned& r1, unsigned addr) {
    asm volatile("ldmatrix.sync.aligned.m8n8.x2.shared.b16 {%0,%1}, [%2];"
        : "=r"(r0), "=r"(r1) : "r"(addr));
}
__device__ __forceinline__ void mma16816(float* c, const unsigned* a,
                                         unsigned b0, unsigned b1) {
    asm volatile("mma.sync.aligned.m16n8k16.row.col.f32.bf16.bf16.f32 "
        "{%0,%1,%2,%3}, {%4,%5,%6,%7}, {%8,%9}, {%0,%1,%2,%3};"
        : "+f"(c[0]), "+f"(c[1]), "+f"(c[2]), "+f"(c[3])
        : "r"(a[0]), "r"(a[1]), "r"(a[2]), "r"(a[3]), "r"(b0), "r"(b1));
}

// ---------------- lens: count nonzero tokens per row -------------------
__global__ void k_lens(const int* __restrict__ text, float* __restrict__ out_lens) {
    int b = blockIdx.x, lane = threadIdx.x;
    int cnt = 0;
    for (int s = lane; s < Sn; s += 32) cnt += (text[b*Sn + s] != 0);
    for (int o = 16; o > 0; o >>= 1) cnt += __shfl_down_sync(0xffffffffu, cnt, o);
    if (lane == 0) { g_lens[b] = cnt; out_lens[b] = (float)cnt; }
}

// -------- prep: gathered embeddings -> hi/lo bf16 ----------------------
__global__ __launch_bounds__(128) void k_prepX(const int* __restrict__ text,
                                               const float* __restrict__ emb) {
    int m = blockIdx.x * 128 + threadIdx.x;     // 256 blocks
    int tok = text[m];
    const float4* er = (const float4*)(emb + (long)tok * EMBn);
    uint4* dh = ((uint4*)g_xc_hi) + (long)m * 16;
    uint4* dl = ((uint4*)g_xc_lo) + (long)m * 16;
    #pragma unroll 4
    for (int i = 0; i < 16; i++) {
        float4 a = er[2*i], b = er[2*i+1];
        float2 p0 = make_float2(a.x, a.y), p1 = make_float2(a.z, a.w);
        float2 p2 = make_float2(b.x, b.y), p3 = make_float2(b.z, b.w);
        __nv_bfloat162 h0 = __float22bfloat162_rn(p0);
        __nv_bfloat162 h1 = __float22bfloat162_rn(p1);
        __nv_bfloat162 h2 = __float22bfloat162_rn(p2);
        __nv_bfloat162 h3 = __float22bfloat162_rn(p3);
        float2 f0 = __bfloat1622float2(h0), f1 = __bfloat1622float2(h1);
        float2 f2 = __bfloat1622float2(h2), f3 = __bfloat1622float2(h3);
        __nv_bfloat162 l0 = __float22bfloat162_rn(make_float2(p0.x-f0.x, p0.y-f0.y));
        __nv_bfloat162 l1 = __float22bfloat162_rn(make_float2(p1.x-f1.x, p1.y-f1.y));
        __nv_bfloat162 l2 = __float22bfloat162_rn(make_float2(p2.x-f2.x, p2.y-f2.y));
        __nv_bfloat162 l3 = __float22bfloat162_rn(make_float2(p3.x-f3.x, p3.y-f3.y));
        uint4 uh, ul;
        uh.x = *(unsigned*)&h0; uh.y = *(unsigned*)&h1;
        uh.z = *(unsigned*)&h2; uh.w = *(unsigned*)&h3;
        ul.x = *(unsigned*)&l0; ul.y = *(unsigned*)&l1;
        ul.z = *(unsigned*)&l2; ul.w = *(unsigned*)&l3;
        dh[i] = uh; dl[i] = ul;
    }
}

// -------- prep: W^T -> hi/lo bf16, one thread per element --------------
__global__ __launch_bounds__(256) void k_prepW(const float* __restrict__ Wf,
                                               const float* __restrict__ Wb) {
    int gid = blockIdx.x * 256 + threadIdx.x;   // 1024 blocks -> 262144
    int k = gid & 127;
    int n = (gid >> 7) & 1023;
    int d = gid >> 17;
    const float* W = d ? Wb : Wf;
    float v = W[k * G4 + n];
    __nv_bfloat16 h = __float2bfloat16_rn(v);
    long o = ((long)(d*1024 + n))*128 + k;
    g_wt_hi[o] = h;
    g_wt_lo[o] = __float2bfloat16_rn(v - __bfloat162float(h));
}

// -------- prep: U reorder (n' = unit*4+gate), one thread per element ----
__global__ __launch_bounds__(256) void k_prepU(const float* __restrict__ Uf,
                                               const float* __restrict__ Ub) {
    int gid = blockIdx.x * 256 + threadIdx.x;   // 2048 blocks -> 524288
    int k  = gid & 255;
    int np = (gid >> 8) & 1023;
    int d  = gid >> 18;
    int j = np >> 2, g = np & 3;
    const float* U = d ? Ub : Uf;
    float v = U[k * G4 + g*256 + j];
    __nv_bfloat16 h = __float2bfloat16_rn(v);
    long o = ((long)(d*1024 + np))*256 + k;
    g_u2h[o] = h;
    g_u2l[o] = __float2bfloat16_rn(v - __bfloat162float(h));
}

// -------- tensor input GEMM via mma.sync (split-bf16) — R9 proven ------
#define TGA 0
#define TGB0 34816
#define TGB1 69632
#define TG_SMEM 104448

__global__ __launch_bounds__(256) void k_tgemm(const float* __restrict__ bf_,
                                               const float* __restrict__ bb_) {
    extern __shared__ char smem[];
    unsigned sb = smem_u32(smem);
    int tid = threadIdx.x, wid = tid >> 5, lane = tid & 31;
    int wr = wid >> 1, wc = wid & 1;
    int m0 = blockIdx.y * 128;
    int n0 = blockIdx.x * 128;
    int d  = n0 >> 10, gg0 = n0 & 1023;

    {
        int row = tid >> 1, half = tid & 1;
        const uint4* s0 = ((const uint4*)g_wt_hi) + (long)(d*1024 + gg0 + row)*16 + half*8;
        const uint4* s1 = ((const uint4*)g_wt_lo) + (long)(d*1024 + gg0 + row)*16 + half*8;
        uint4* d0 = (uint4*)(smem + TGB0 + row*272 + half*128);
        uint4* d1 = (uint4*)(smem + TGB1 + row*272 + half*128);
        #pragma unroll
        for (int i = 0; i < 8; i++) { d0[i] = s0[i]; d1[i] = s1[i]; }
    }
    {
        int row = tid >> 1, half = tid & 1;
        const uint4* s = ((const uint4*)g_xc_hi) + (long)(m0 + row)*16 + half*8;
        uint4* dA = (uint4*)(smem + TGA + row*272 + half*128);
        #pragma unroll
        for (int i = 0; i < 8; i++) dA[i] = s[i];
    }
    __syncthreads();

    float acc[2][8][4];
    #pragma unroll
    for (int mi = 0; mi < 2; mi++)
        #pragma unroll
        for (int nj = 0; nj < 8; nj++)
            #pragma unroll
            for (int q = 0; q < 4; q++) acc[mi][nj][q] = 0.f;

    unsigned a_row = (unsigned)(wr*32 + (lane & 15));
    unsigned b_rowbase = (unsigned)(wc*64 + (lane & 7));
    unsigned a_koff = (unsigned)((lane >> 4) * 8);
    unsigned b_koff = (unsigned)(((lane >> 3) & 1) * 8);

    #pragma unroll 1
    for (int phase = 0; phase < 2; phase++) {
        if (phase == 1) {
            __syncthreads();
            int row = tid >> 1, half = tid & 1;
            const uint4* s = ((const uint4*)g_xc_lo) + (long)(m0 + row)*16 + half*8;
            uint4* dA = (uint4*)(smem + TGA + row*272 + half*128);
            #pragma unroll
            for (int i = 0; i < 8; i++) dA[i] = s[i];
            __syncthreads();
        }
        #pragma unroll
        for (int kt = 0; kt < 8; kt++) {
            unsigned a0[4], a1[4];
            unsigned aaddr = sb + TGA + a_row*272 + (kt*16 + a_koff)*2;
            ldsm4(a0, aaddr);
            ldsm4(a1, aaddr + 16*272);
            #pragma unroll
            for (int nj = 0; nj < 8; nj++) {
                unsigned boff = (b_rowbase + nj*8)*272 + (kt*16 + b_koff)*2;
                unsigned b0, b1;
                ldsm2(b0, b1, sb + TGB0 + boff);
                mma16816(acc[0][nj], a0, b0, b1);
                mma16816(acc[1][nj], a1, b0, b1);
                if (phase == 0) {
                    unsigned c0, c1;
                    ldsm2(c0, c1, sb + TGB1 + boff);
                    mma16816(acc[0][nj], a0, c0, c1);
                    mma16816(acc[1][nj], a1, c0, c1);
                }
            }
        }
    }

    const float* bias = d ? bb_ : bf_;
    #pragma unroll
    for (int mi = 0; mi < 2; mi++) {
        int m = m0 + wr*32 + mi*16 + (lane >> 2);
        float* rowp = g_xz + ((long)d*32768 + m)*G4;
        #pragma unroll
        for (int nj = 0; nj < 8; nj++) {
            int gg = gg0 + wc*64 + nj*8 + (lane & 3)*2;
            float bx = bias[gg], by = bias[gg+1];
            float2 v0, v1;
            v0.x = acc[mi][nj][0] + bx; v0.y = acc[mi][nj][1] + by;
            v1.x = acc[mi][nj][2] + bx; v1.y = acc[mi][nj][3] + by;
            *(float2*)(rowp + gg)          = v0;
            *(float2*)(rowp + 8*G4 + gg)   = v1;
        }
    }
}

// ------------------- tensor-core persistent BiLSTM (R11 + flag barrier) -
// 128 blocks = (d, hg 0..15, bg 0..3), 256 threads = 8 warps (one n8 tile
// each). Block: dir d, units [hg*16,+16), batches [bg*16,+16). B (U')
// fragments register-resident (64 regs). Barrier: flag array per group
// (16 parallel pollers), publish after single-thread fence; wait at next
// iteration start overlapped with x prefetch.
#define LS_U   0                     // U' stage: 64 rows * 528 B * 2 (hi,lo)
#define LS_AHH 67584                 // 16 * 528
#define LS_AHL (67584 + 8448)
#define LS_SMEM (67584 + 2*8448)

__global__ __launch_bounds__(256) void k_lstm() {
    extern __shared__ char smem[];
    unsigned sb = smem_u32(smem);

    int blk = blockIdx.x;
    int d  = blk >> 6;
    int hg = (blk >> 2) & 15;
    int bg = blk & 3;
    int b0 = bg * 16;
    int gid = d*4 + bg;

    int tid = threadIdx.x, wid = tid >> 5, lane = tid & 31;
    int nj = wid;

    // stage U' rows [hg*64, +64), hi+lo
    for (int i = tid; i < 64*32; i += 256) {
        int row = i >> 5, c = i & 31;
        long src = ((long)(d*1024 + hg*64 + row)) * 256;
        *(uint4*)(smem + LS_U + row*528 + c*16)          = *(((const uint4*)(g_u2h + src)) + c);
        *(uint4*)(smem + LS_U + 64*528 + row*528 + c*16) = *(((const uint4*)(g_u2l + src)) + c);
    }
    // zero A staging (h0 = 0): 2112 floats each
    for (int i = tid; i < 2112; i += 256) {
        *(float*)(smem + LS_AHH + i*4) = 0.f;
        *(float*)(smem + LS_AHL + i*4) = 0.f;
    }
    __syncthreads();

    // preload B fragments (64 regs)
    unsigned bh[16][2], bl[16][2];
    {
        unsigned brow = (unsigned)(nj*8 + (lane & 7));
        unsigned koff = (unsigned)(((lane >> 3) & 1) * 8);
        #pragma unroll
        for (int kt = 0; kt < 16; kt++) {
            ldsm2(bh[kt][0], bh[kt][1], sb + LS_U + brow*528 + (kt*16 + koff)*2);
            ldsm2(bl[kt][0], bl[kt][1], sb + LS_U + 64*528 + brow*528 + (kt*16 + koff)*2);
        }
    }

    int row = lane >> 2;
    int p   = lane & 3;
    int jj  = nj*2 + (p >> 1);
    int jgl = hg*16 + jj;
    bool fin = (lane & 1) == 0;
    float cst0 = 0.f, cst1 = 0.f;

    unsigned a_row = (unsigned)(lane & 15);
    unsigned a_koff = (unsigned)((lane >> 4) * 8);
    unsigned aoff = a_row*528 + a_koff*2;

    for (int r = 0; r < Sn; r++) {
        int s = d ? (Sn-1-r) : r;

        // prefetch x (even lanes) — independent of peer flags
        float x0=0,x1=0,x2=0,x3=0,x4=0,x5=0,x6=0,x7=0;
        if (fin) {
            const float* xp = g_xz + (((long)(d*64 + b0 + row))*Sn + s)*G4 + jgl;
            x0 = __ldg(xp);       x1 = __ldg(xp + 256);
            x2 = __ldg(xp + 512); x3 = __ldg(xp + 768);
            const float* xq = xp + (long)8*Sn*G4;
            x4 = __ldg(xq);       x5 = __ldg(xq + 256);
            x6 = __ldg(xq + 512); x7 = __ldg(xq + 768);
        }
        // wait peers reached step r, then stage prev h (hi/lo)
        if (r > 0) {
            if (tid < 16) {
                volatile int* f = &g_flags[gid][tid];
                while (*f < r) { }
            }
            __syncthreads();
            int sp = d ? (s+1) : (s-1);
            #pragma unroll
            for (int i = 0; i < 2; i++) {
                int l = i*256 + tid;
                int ar = l >> 5, c = l & 31;
                long src = (((long)(d*64 + b0 + ar))*Sn + sp)*HIDn;
                *(uint4*)(smem + LS_AHH + ar*528 + c*16) = __ldcg(((const uint4*)(g_hx_hi + src)) + c);
                *(uint4*)(smem + LS_AHL + ar*528 + c*16) = __ldcg(((const uint4*)(g_hx_lo + src)) + c);
            }
        }
        __syncthreads();

        float aA[4] = {0,0,0,0}, aB[4] = {0,0,0,0}, aC[4] = {0,0,0,0};
        #pragma unroll
        for (int kt = 0; kt < 16; kt++) {
            unsigned ah[4], al[4];
            ldsm4(ah, sb + LS_AHH + aoff + kt*32);
            mma16816(aA, ah, bh[kt][0], bh[kt][1]);
            mma16816(aB, ah, bl[kt][0], bl[kt][1]);
            ldsm4(al, sb + LS_AHL + aoff + kt*32);
            mma16816(aC, al, bh[kt][0], bh[kt][1]);
        }

        float acc0 = aA[0]+aB[0]+aC[0], acc1 = aA[1]+aB[1]+aC[1];
        float acc2 = aA[2]+aB[2]+aC[2], acc3 = aA[3]+aB[3]+aC[3];
        float rc0 = __shfl_xor_sync(0xffffffffu, acc0, 1);
        float rc1 = __shfl_xor_sync(0xffffffffu, acc1, 1);
        float rc2 = __shfl_xor_sync(0xffffffffu, acc2, 1);
        float rc3 = __shfl_xor_sync(0xffffffffu, acc3, 1);

        if (fin) {
            {   // batch b0+row
                float zi = x0 + acc0, zf = x1 + acc1;
                float zg = x2 + rc0,  zo = x3 + rc1;
                float ig = 1.f/(1.f+__expf(-zi)), fg = 1.f/(1.f+__expf(-zf));
                float gv = tanhf(zg), og = 1.f/(1.f+__expf(-zo));
                cst0 = fg*cst0 + ig*gv;
                float hv = og * tanhf(cst0);
                long o0 = (((long)(d*64 + b0 + row))*Sn + s)*HIDn + jgl;
                g_hall[o0] = hv;
                __nv_bfloat16 hh = __float2bfloat16_rn(hv);
                g_hx_hi[o0] = hh;
                g_hx_lo[o0] = __float2bfloat16_rn(hv - __bfloat162float(hh));
            }
            {   // batch b0+row+8
                float zi = x4 + acc2, zf = x5 + acc3;
                float zg = x6 + rc2,  zo = x7 + rc3;
                float ig = 1.f/(1.f+__expf(-zi)), fg = 1.f/(1.f+__expf(-zf));
                float gv = tanhf(zg), og = 1.f/(1.f+__expf(-zo));
                cst1 = fg*cst1 + ig*gv;
                float hv = og * tanhf(cst1);
                long o1 = (((long)(d*64 + b0 + row + 8))*Sn + s)*HIDn + jgl;
                g_hall[o1] = hv;
                __nv_bfloat16 hh = __float2bfloat16_rn(hv);
                g_hx_hi[o1] = hh;
                g_hx_lo[o1] = __float2bfloat16_rn(hv - __bfloat162float(hh));
            }
        }

        // publish completion of step r (single-thread fence + flag store)
        __syncthreads();
        if (tid == 0) {
            __threadfence();
            *((volatile int*)&g_flags[gid][hg]) = r + 1;
        }
    }
}

// ---------------- logits = [h_fwd ; h_bwd] @ W_d + b_d ------------------
__global__ __launch_bounds__(256) void k_logits(
    const float* __restrict__ Wd, const float* __restrict__ bd,
    float* __restrict__ out)
{
    __shared__ float Wd_s[512*NTAG];
    int tid = threadIdx.x;
    for (int i = tid; i < 512*NTAG; i += 256) Wd_s[i] = Wd[i];
    __syncthreads();

    int wid = tid >> 5, lane = tid & 31;
    long m = (long)blockIdx.x * 8 + wid;

    float acc[NTAG];
    #pragma unroll
    for (int t = 0; t < NTAG; t++) acc[t] = 0.f;

    for (int k = lane; k < 512; k += 32) {
        int dd = k >> 8, jj = k & 255;
        float hv = g_hall[((long)dd*32768 + m)*HIDn + jj];
        #pragma unroll
        for (int t = 0; t < NTAG; t++) acc[t] += hv * Wd_s[k*NTAG + t];
    }
    #pragma unroll
    for (int t = 0; t < NTAG; t++)
        for (int o = 16; o > 0; o >>= 1)
            acc[t] += __shfl_down_sync(0xffffffffu, acc[t], o);
    if (lane == 0) {
        #pragma unroll
        for (int t = 0; t < NTAG; t++) out[m*NTAG + t] = acc[t] + bd[t];
    }
}

// --------------------------- CRF (warp per batch) -----------------------
__global__ __launch_bounds__(256) void k_crf(
    const float* __restrict__ logits, const int* __restrict__ labels,
    const float* __restrict__ trans, float* __restrict__ out_ll)
{
    __shared__ float tr[81];
    __shared__ float alpha[8][12];
    int tid = threadIdx.x;
    if (tid < 81) tr[tid] = trans[tid];
    __syncthreads();

    int wid = tid >> 5, lane = tid & 31;
    int b = blockIdx.x * 8 + wid;
    int len = g_lens[b];
    const float* lg = logits + (long)b * Sn * NTAG;
    const int*   lb = labels + (long)b * Sn;

    float sc = 0.f;
    for (int t = lane; t < Sn; t += 32) {
        int y = lb[t];
        if (t < len)     sc += lg[t*NTAG + y];
        if (t < len - 1) sc += tr[y*NTAG + lb[t+1]];
    }
    for (int o = 16; o > 0; o >>= 1) sc += __shfl_down_sync(0xffffffffu, sc, o);
    sc = __shfl_sync(0xffffffffu, sc, 0);

    if (lane < NTAG) alpha[wid][lane] = lg[lane];
    __syncwarp();
    for (int t = 1; t < Sn; t++) {
        if (t >= len) break;
        float na = 0.f;
        if (lane < NTAG) {
            float mx = -1e30f;
            #pragma unroll
            for (int i = 0; i < NTAG; i++) {
                float v = alpha[wid][i] + tr[i*NTAG + lane];
                mx = fmaxf(mx, v);
            }
            float s = 0.f;
            #pragma unroll
            for (int i = 0; i < NTAG; i++)
                s += __expf(alpha[wid][i] + tr[i*NTAG + lane] - mx);
            na = mx + __logf(s) + lg[t*NTAG + lane];
        }
        __syncwarp();
        if (lane < NTAG) alpha[wid][lane] = na;
        __syncwarp();
    }
    if (lane == 0) {
        float mx = -1e30f;
        for (int i = 0; i < NTAG; i++) mx = fmaxf(mx, alpha[wid][i]);
        float s = 0.f;
        for (int i = 0; i < NTAG; i++) s += __expf(alpha[wid][i] - mx);
        out_ll[b] = sc - (mx + __logf(s));
    }
}

// ----------------------------------------------------------------------
extern "C" void kernel_launch(void* const* d_in, const int* in_sizes, int n_in,
                              void* d_out, int out_size)
{
    const int*   text  = (const int*)  d_in[0];
    const int*   labels= (const int*)  d_in[1];
    const float* emb   = (const float*)d_in[2];
    const float* Wf    = (const float*)d_in[3];
    const float* Uf    = (const float*)d_in[4];
    const float* bf    = (const float*)d_in[5];
    const float* Wb    = (const float*)d_in[6];
    const float* Ub    = (const float*)d_in[7];
    const float* bb    = (const float*)d_in[8];
    const float* Wd    = (const float*)d_in[9];
    const float* bd    = (const float*)d_in[10];
    const float* trans = (const float*)d_in[11];

    float* out        = (float*)d_out;
    float* out_logits = out;                         // 64*512*9
    float* out_lens   = out + 64ll*512*9;            // 64
    float* out_ll     = out_lens + 64;               // 64

    cudaFuncSetAttribute(k_lstm, cudaFuncAttributeMaxDynamicSharedMemorySize, LS_SMEM);
    cudaFuncSetAttribute(k_tgemm, cudaFuncAttributeMaxDynamicSharedMemorySize, TG_SMEM);

    k_reset<<<1, 128>>>();
    k_lens<<<64, 32>>>(text, out_lens);
    k_prepW<<<1024, 256>>>(Wf, Wb);
    k_prepU<<<2048, 256>>>(Uf, Ub);
    k_prepX<<<256, 128>>>(text, emb);
    dim3 tg(16, 256);
    k_tgemm<<<tg, 256, TG_SMEM>>>(bf, bb);
    k_lstm<<<128, 256, LS_SMEM>>>();
    k_logits<<<4096, 256>>>(Wd, bd, out_logits);
    k_crf<<<8, 256>>>(out_logits, labels, trans, out_ll);
}